// round 11
// baseline (speedup 1.0000x reference)
#include <cuda_runtime.h>
#include <cuda_bf16.h>
#include <cstddef>

// Problem shapes (fixed per reference setup_inputs):
//   idx:    [B, 2, N] f32,  B=16, N = 512*512 = 262144
//   source: [B, 640, 640, 3] f32
//   out:    [B, 512, 512, 3] f32
static constexpr int B_    = 16;
static constexpr int HS    = 640;
static constexpr int WS    = 640;
static constexpr int C_    = 3;
static constexpr int NPIX  = 512 * 512;                  // 262144 per batch
static constexpr long long NTOT = (long long)B_ * NPIX;  // 4,194,304

// Branchless predicated vector loads. Single @p LDG instructions: no
// BSSY/BSYNC, freely schedulable by ptxas (restores front-batched MLP that
// the C-level `if` destroyed in the previous round). Predicated-off lanes
// keep the zero-initialized registers ("+f" read-write constraints).
__device__ __forceinline__ float4 ldg128_pred(const float* p, int pred) {
    float4 r = make_float4(0.f, 0.f, 0.f, 0.f);
    asm("{\n\t"
        ".reg .pred lp;\n\t"
        "setp.ne.s32 lp, %5, 0;\n\t"
        "@lp ld.global.nc.v4.f32 {%0,%1,%2,%3}, [%4];\n\t"
        "}"
        : "+f"(r.x), "+f"(r.y), "+f"(r.z), "+f"(r.w)
        : "l"(p), "r"(pred));
    return r;
}

__device__ __forceinline__ float2 ldg64_pred(const float* p, int pred) {
    float2 r = make_float2(0.f, 0.f);
    asm("{\n\t"
        ".reg .pred lp;\n\t"
        "setp.ne.s32 lp, %3, 0;\n\t"
        "@lp ld.global.nc.v2.f32 {%0,%1}, [%2];\n\t"
        "}"
        : "+f"(r.x), "+f"(r.y)
        : "l"(p), "r"(pred));
    return r;
}

// Gather scheme (1.5 avg L1 wavefronts/pixel):
//   always (if valid):   LDG.128 at f = s & ~3   (16B-aligned, 1 sector)
//   iff valid && m >= 2: LDG.64  at f + 4        (~half the lanes, predicated)
// s = 3*(ir*640+ic), m = s & 3 uniform over {0..3}. [f, f+3] covers [s, s+2]
// for m <= 1; [f, f+5] covers it for m >= 2. Max touched element:
// m>=2 -> f+5 = s+3 or s+2 <= 1228797 < 640*640*3; m<=1 -> f+3 <= 1228799.
// Reassembly: c_k = w[m+k], w = {A.x,A.y,A.z,A.w,B.x,B.y} via SELs; invalid
// pixels yield zeros automatically (both loads predicated off -> zero regs).
__global__ void __launch_bounds__(256) nn_gather_kernel(
    const float* __restrict__ idx,
    const float* __restrict__ src,
    float* __restrict__ out)
{
    long long g = (long long)blockIdx.x * blockDim.x + threadIdx.x;
    long long p0 = g * 4;                 // first pixel of this group
    if (p0 >= NTOT) return;

    int b = (int)(p0 / NPIX);
    int n = (int)(p0 - (long long)b * NPIX);   // NPIX % 4 == 0 -> group stays in one batch

    const float* idx_b = idx + (size_t)b * 2 * NPIX;
    // idx is touched exactly once: stream it (evict-first) so it doesn't
    // evict the randomly-reused source image from L2.
    float4 rows = __ldcs(reinterpret_cast<const float4*>(idx_b + n));
    float4 cols = __ldcs(reinterpret_cast<const float4*>(idx_b + NPIX + n));

    const float* sb = src + (size_t)b * HS * WS * C_;

    float rf[4] = {rows.x, rows.y, rows.z, rows.w};
    float cf[4] = {cols.x, cols.y, cols.z, cols.w};

    // Phase 1: all addresses + predicates (pure ALU, no memory).
    int fv[4], mv[4], pa[4], pb[4];
#pragma unroll
    for (int i = 0; i < 4; ++i) {
        // trunc(x + 0.5) toward zero, exactly like jnp.trunc(...).astype(int32)
        int ir = (int)(rf[i] + 0.5f);
        int ic = (int)(cf[i] + 0.5f);
        int valid = (ir >= 0) & (ic >= 0) & (ir < HS) & (ic < WS);
        int s = (ir * WS + ic) * C_;
        fv[i] = s & ~3;
        mv[i] = s & 3;
        pa[i] = valid;
        pb[i] = valid & (mv[i] >> 1);     // valid && m >= 2
    }

    // Phase 2: all gather loads, front-batched (MLP = up to 8 in flight).
    float4 A[4];
    float2 Bv[4];
#pragma unroll
    for (int i = 0; i < 4; ++i)
        A[i] = ldg128_pred(sb + fv[i], pa[i]);
#pragma unroll
    for (int i = 0; i < 4; ++i)
        Bv[i] = ldg64_pred(sb + fv[i] + 4, pb[i]);

    // Phase 3: reassemble c_k = w[m+k].
    float v[12];
#pragma unroll
    for (int i = 0; i < 4; ++i) {
        bool m1 = (mv[i] & 1) != 0;
        bool m2 = (mv[i] & 2) != 0;
        // w[m]   : 0->A.x 1->A.y 2->A.z 3->A.w
        v[i * 3 + 0] = m2 ? (m1 ? A[i].w : A[i].z) : (m1 ? A[i].y : A[i].x);
        // w[m+1] : 0->A.y 1->A.z 2->A.w 3->B.x
        v[i * 3 + 1] = m2 ? (m1 ? Bv[i].x : A[i].w) : (m1 ? A[i].z : A[i].y);
        // w[m+2] : 0->A.z 1->A.w 2->B.x 3->B.y
        v[i * 3 + 2] = m2 ? (m1 ? Bv[i].y : Bv[i].x) : (m1 ? A[i].w : A[i].z);
    }

    // out is write-once: streaming stores keep L2 for the source image.
    float4* o = reinterpret_cast<float4*>(out + (size_t)p0 * 3);
    __stcs(o + 0, make_float4(v[0], v[1], v[2],  v[3]));
    __stcs(o + 1, make_float4(v[4], v[5], v[6],  v[7]));
    __stcs(o + 2, make_float4(v[8], v[9], v[10], v[11]));
}

extern "C" void kernel_launch(void* const* d_in, const int* in_sizes, int n_in,
                              void* d_out, int out_size)
{
    const float* idx = (const float*)d_in[0];   // [16, 2, 262144] f32
    const float* src = (const float*)d_in[1];   // [16, 640, 640, 3] f32
    float* out = (float*)d_out;                 // [16, 512, 512, 3] f32

    (void)in_sizes; (void)n_in; (void)out_size;

    const long long n_groups = NTOT / 4;        // 1,048,576
    const int threads = 256;
    const int blocks = (int)((n_groups + threads - 1) / threads);  // 4096
    nn_gather_kernel<<<blocks, threads>>>(idx, src, out);
}

// round 16
// speedup vs baseline: 1.3136x; 1.3136x over previous
#include <cuda_runtime.h>
#include <cuda_bf16.h>
#include <cstddef>

// Problem shapes (fixed per reference setup_inputs):
//   idx:    [B, 2, N] f32,  B=16, N = 512*512 = 262144
//   source: [B, 640, 640, 3] f32
//   out:    [B, 512, 512, 3] f32
static constexpr int B_    = 16;
static constexpr int HS    = 640;
static constexpr int WS    = 640;
static constexpr int C_    = 3;
static constexpr int NPIX  = 512 * 512;                  // 262144 per batch
static constexpr long long NTOT = (long long)B_ * NPIX;  // 4,194,304

// Empirically established (R1/R3/R4/R5 profiles): scattered-gather L1 cost is
// 1 wavefront per lane per LDG.32/LDG.64, ~2 per lane for LDG.128, predication
// does not reduce it, and .nc adds ~10%. => 2x plain LDG.64 per pixel (R3
// scheme) is the wavefront floor for this layout. This round keeps that exact
// scheme but FRONT-BATCHES the 8 loads per thread (phase-split: addresses ->
// loads -> selects) to raise per-thread MLP from ~2 to 8 and close the
// latency exposure suggested by L1=69% / issue=11% in the R3 profile.
//
// Validity is folded into the address (select-to-dummy sb+0): no divergent
// branch, invalid lanes (~17%) coalesce into one broadcast wavefront, and the
// final select tree zeroes them.
//
// Coverage/bounds: s = 3*(ir*640+ic), e = s & ~1 (8B-aligned). [e, e+3]
// always covers [s, s+2]; max touched element e+3 <= 1228799 < 640*640*3.
__global__ void __launch_bounds__(256) nn_gather_kernel(
    const float* __restrict__ idx,
    const float* __restrict__ src,
    float* __restrict__ out)
{
    long long g = (long long)blockIdx.x * blockDim.x + threadIdx.x;
    long long p0 = g * 4;                 // first pixel of this group
    if (p0 >= NTOT) return;

    int b = (int)(p0 / NPIX);
    int n = (int)(p0 - (long long)b * NPIX);   // NPIX % 4 == 0 -> group stays in one batch

    const float* idx_b = idx + (size_t)b * 2 * NPIX;
    float4 rows = *reinterpret_cast<const float4*>(idx_b + n);
    float4 cols = *reinterpret_cast<const float4*>(idx_b + NPIX + n);

    const float* sb = src + (size_t)b * HS * WS * C_;

    float rf[4] = {rows.x, rows.y, rows.z, rows.w};
    float cf[4] = {cols.x, cols.y, cols.z, cols.w};

    // Phase 1: addresses + flags (pure ALU, no memory).
    int off[4];
    int odd[4];
    int val[4];
#pragma unroll
    for (int i = 0; i < 4; ++i) {
        // trunc(x + 0.5) toward zero, exactly like jnp.trunc(...).astype(int32)
        int ir = (int)(rf[i] + 0.5f);
        int ic = (int)(cf[i] + 0.5f);
        int valid = (ir >= 0) & (ic >= 0) & (ir < HS) & (ic < WS);
        int s = (ir * WS + ic) * C_;       // 4B-aligned element index
        int e = s & ~1;                    // 8B-aligned; [e, e+3] covers [s, s+2]
        off[i] = valid ? e : 0;            // invalid lanes -> shared dummy line
        odd[i] = s & 1;
        val[i] = valid;
    }

    // Phase 2: all 8 LDG.64 issued back-to-back -> MLP = 8 in flight.
    float2 A[4], Bv[4];
#pragma unroll
    for (int i = 0; i < 4; ++i) {
        A[i]  = *reinterpret_cast<const float2*>(sb + off[i]);      // e, e+1
        Bv[i] = *reinterpret_cast<const float2*>(sb + off[i] + 2);  // e+2, e+3
    }

    // Phase 3: parity selects + validity zeroing.
    float v[12];
#pragma unroll
    for (int i = 0; i < 4; ++i) {
        bool o = odd[i] != 0;
        float c0 = o ? A[i].y  : A[i].x;
        float c1 = o ? Bv[i].x : A[i].y;
        float c2 = o ? Bv[i].y : Bv[i].x;
        bool k = val[i] != 0;
        v[i * 3 + 0] = k ? c0 : 0.0f;
        v[i * 3 + 1] = k ? c1 : 0.0f;
        v[i * 3 + 2] = k ? c2 : 0.0f;
    }

    float4* o4 = reinterpret_cast<float4*>(out + (size_t)p0 * 3);
    o4[0] = make_float4(v[0], v[1], v[2],  v[3]);
    o4[1] = make_float4(v[4], v[5], v[6],  v[7]);
    o4[2] = make_float4(v[8], v[9], v[10], v[11]);
}

extern "C" void kernel_launch(void* const* d_in, const int* in_sizes, int n_in,
                              void* d_out, int out_size)
{
    const float* idx = (const float*)d_in[0];   // [16, 2, 262144] f32
    const float* src = (const float*)d_in[1];   // [16, 640, 640, 3] f32
    float* out = (float*)d_out;                 // [16, 512, 512, 3] f32

    (void)in_sizes; (void)n_in; (void)out_size;

    const long long n_groups = NTOT / 4;        // 1,048,576
    const int threads = 256;
    const int blocks = (int)((n_groups + threads - 1) / threads);  // 4096
    nn_gather_kernel<<<blocks, threads>>>(idx, src, out);
}